// round 13
// baseline (speedup 1.0000x reference)
#include <cuda_runtime.h>
#include <cstdint>

#define BB 4
#define SS 1024
#define HH 32
#define DD 8
#define EE 256
#define KH 8                                   // split-K factor
#define KT (SS / KH)                           // 128 keys per tile
constexpr int NROWS = BB * SS * HH;            // 131072
constexpr int NQ = BB * HH * SS;               // 131072 (rows x heads)

// Scratch (allocation-free rule: __device__ globals)
__device__ float g_att[BB * SS * EE];          // [B,S,E] attention out, 4 MB
__device__ float g_po[KH][NQ][8];              // split-K partial o, 33.5 MB
__device__ float g_pl[KH][NQ];                 // split-K partial l, 4 MB

// ---------- packed f32x2 helpers (Blackwell dual FP32 datapath) ----------
__device__ __forceinline__ unsigned long long pack2(float lo, float hi) {
    unsigned long long r;
    asm("mov.b64 %0, {%1, %2};" : "=l"(r) : "f"(lo), "f"(hi));
    return r;
}
__device__ __forceinline__ void unpack2(unsigned long long v, float& lo, float& hi) {
    asm("mov.b64 {%0, %1}, %2;" : "=f"(lo), "=f"(hi) : "l"(v));
}
__device__ __forceinline__ unsigned long long ffma2(unsigned long long a,
                                                    unsigned long long b,
                                                    unsigned long long c) {
    unsigned long long d;
    asm("fma.rn.f32x2 %0, %1, %2, %3;" : "=l"(d) : "l"(a), "l"(b), "l"(c));
    return d;
}
__device__ __forceinline__ unsigned long long fadd2(unsigned long long a,
                                                    unsigned long long b) {
    unsigned long long d;
    asm("add.rn.f32x2 %0, %1, %2;" : "=l"(d) : "l"(a), "l"(b));
    return d;
}
__device__ __forceinline__ float ex2(float x) {
    float y;
    asm("ex2.approx.ftz.f32 %0, %1;" : "=f"(y) : "f"(x));
    return y;
}

// ---------------------------------------------------------------------------
// Attention, split-K(8) + 2 queries/thread. R12's verified inner loop;
// only the work decomposition changed (4096 blocks -> 4.6 waves, finer
// tail). Circuit closed form:
//   <Z_w> = prod_{j=0..w} cos(x_j+th_j) (w>=1), <Z_0> = prod_{j=1..7}.
// Grid (128 heads, 4 q-slabs, 8 key-eighths) x 128 threads.
// Phase 1: 128-key tile, pair-packed sF[p*16 + 2d + lane] (4 KB), 1 row/thr.
// Phase 2: per key-pair load (4 x LDS.128, shared by both queries):
// per query an 8-step ffma2 chain -> two dots, ex2/lane, AV lane partials.
// |score| <= sqrt(8): no max subtraction. Unnormalized partials out.
// ---------------------------------------------------------------------------
__global__ void __launch_bounds__(128) attn_kernel(const float* __restrict__ x,
                                                   const float* __restrict__ theta) {
    __shared__ float sF[KT * 8];    // 4 KB pair-packed key tile

    int bh   = blockIdx.x;          // 0..127 (b*32 + h)
    int slab = blockIdx.y;          // 0..3 (256 queries each)
    int kh   = blockIdx.z;          // 0..7 key eighth
    int tid  = threadIdx.x;
    int b = bh >> 5, h = bh & 31;

    float th[8];
#pragma unroll
    for (int d = 0; d < 8; d++) th[d] = theta[d];

    // Phase 1: key tile (128 rows, exactly 1 per thread)
    {
        int j = tid;                // local row
        int row = kh * KT + j;
        const float4* gx = reinterpret_cast<const float4*>(
            x + ((size_t)(b * SS + row) * EE + h * DD));
        float4 xa = gx[0];
        float4 xb = gx[1];

        float c[8];
        c[0] = cosf(xa.x + th[0]);
        c[1] = cosf(xa.y + th[1]);
        c[2] = cosf(xa.z + th[2]);
        c[3] = cosf(xa.w + th[3]);
        c[4] = cosf(xb.x + th[4]);
        c[5] = cosf(xb.y + th[5]);
        c[6] = cosf(xb.z + th[6]);
        c[7] = cosf(xb.w + th[7]);

        float z[8];
        float p = c[0];
#pragma unroll
        for (int w = 1; w < 8; w++) { p *= c[w]; z[w] = p; }
        float s = c[7];
#pragma unroll
        for (int w = 6; w >= 1; w--) s *= c[w];
        z[0] = s;

        int base = (j >> 1) * 16 + (j & 1);
#pragma unroll
        for (int d = 0; d < 8; d++) sF[base + 2 * d] = z[d];
    }

    // This thread's two query rows, computed closed-form directly.
    const float kS = 1.4426950408889634f / 2.8284271247461903f;  // log2(e)/sqrt(8)
    int q0 = slab * 256 + tid * 2;              // queries q0, q0+1
    unsigned long long q2[2][8];
#pragma unroll
    for (int qi = 0; qi < 2; qi++) {
        const float4* gx = reinterpret_cast<const float4*>(
            x + ((size_t)(b * SS + q0 + qi) * EE + h * DD));
        float4 xa = gx[0];
        float4 xb = gx[1];

        float c[8];
        c[0] = cosf(xa.x + th[0]);
        c[1] = cosf(xa.y + th[1]);
        c[2] = cosf(xa.z + th[2]);
        c[3] = cosf(xa.w + th[3]);
        c[4] = cosf(xb.x + th[4]);
        c[5] = cosf(xb.y + th[5]);
        c[6] = cosf(xb.z + th[6]);
        c[7] = cosf(xb.w + th[7]);

        float z[8];
        float p = c[0];
#pragma unroll
        for (int w = 1; w < 8; w++) { p *= c[w]; z[w] = p; }
        float s = c[7];
#pragma unroll
        for (int w = 6; w >= 1; w--) s *= c[w];
        z[0] = s;
#pragma unroll
        for (int d = 0; d < 8; d++) {
            float qv = z[d] * kS;
            q2[qi][d] = pack2(qv, qv);
        }
    }
    __syncthreads();

    unsigned long long o[2][8];
#pragma unroll
    for (int qi = 0; qi < 2; qi++)
#pragma unroll
        for (int d = 0; d < 8; d++) o[qi][d] = 0ULL;
    unsigned long long l2[2] = {0ULL, 0ULL};

    const ulonglong2* kp2 = reinterpret_cast<const ulonglong2*>(sF);

#pragma unroll 2
    for (int p = 0; p < KT / 2; p++) {
        // one key-pair load, shared by both queries
        ulonglong2 w01 = kp2[p * 4 + 0];
        ulonglong2 w23 = kp2[p * 4 + 1];
        ulonglong2 w45 = kp2[p * 4 + 2];
        ulonglong2 w67 = kp2[p * 4 + 3];

        // two independent score chains (ILP)
        unsigned long long s0a = ffma2(q2[0][0], w01.x, 0ULL);
        unsigned long long s1a = ffma2(q2[1][0], w01.x, 0ULL);
        s0a = ffma2(q2[0][1], w01.y, s0a);
        s1a = ffma2(q2[1][1], w01.y, s1a);
        s0a = ffma2(q2[0][2], w23.x, s0a);
        s1a = ffma2(q2[1][2], w23.x, s1a);
        s0a = ffma2(q2[0][3], w23.y, s0a);
        s1a = ffma2(q2[1][3], w23.y, s1a);
        s0a = ffma2(q2[0][4], w45.x, s0a);
        s1a = ffma2(q2[1][4], w45.x, s1a);
        s0a = ffma2(q2[0][5], w45.y, s0a);
        s1a = ffma2(q2[1][5], w45.y, s1a);
        s0a = ffma2(q2[0][6], w67.x, s0a);
        s1a = ffma2(q2[1][6], w67.x, s1a);
        s0a = ffma2(q2[0][7], w67.y, s0a);
        s1a = ffma2(q2[1][7], w67.y, s1a);

        float a0, a1, b0, b1;
        unpack2(s0a, a0, a1);
        unpack2(s1a, b0, b1);
        unsigned long long pp0 = pack2(ex2(a0), ex2(a1));
        unsigned long long pp1 = pack2(ex2(b0), ex2(b1));

        l2[0] = fadd2(l2[0], pp0);
        l2[1] = fadd2(l2[1], pp1);
        o[0][0] = ffma2(pp0, w01.x, o[0][0]);
        o[1][0] = ffma2(pp1, w01.x, o[1][0]);
        o[0][1] = ffma2(pp0, w01.y, o[0][1]);
        o[1][1] = ffma2(pp1, w01.y, o[1][1]);
        o[0][2] = ffma2(pp0, w23.x, o[0][2]);
        o[1][2] = ffma2(pp1, w23.x, o[1][2]);
        o[0][3] = ffma2(pp0, w23.y, o[0][3]);
        o[1][3] = ffma2(pp1, w23.y, o[1][3]);
        o[0][4] = ffma2(pp0, w45.x, o[0][4]);
        o[1][4] = ffma2(pp1, w45.x, o[1][4]);
        o[0][5] = ffma2(pp0, w45.y, o[0][5]);
        o[1][5] = ffma2(pp1, w45.y, o[1][5]);
        o[0][6] = ffma2(pp0, w67.x, o[0][6]);
        o[1][6] = ffma2(pp1, w67.x, o[1][6]);
        o[0][7] = ffma2(pp0, w67.y, o[0][7]);
        o[1][7] = ffma2(pp1, w67.y, o[1][7]);
    }

#pragma unroll
    for (int qi = 0; qi < 2; qi++) {
        float ll, lh;
        unpack2(l2[qi], ll, lh);

        float r[8];
#pragma unroll
        for (int d = 0; d < 8; d++) {
            float lo, hi;
            unpack2(o[qi][d], lo, hi);
            r[d] = lo + hi;
        }

        int rowid = bh * SS + q0 + qi;
        float* po = &g_po[kh][rowid][0];
        *reinterpret_cast<float4*>(po)     = make_float4(r[0], r[1], r[2], r[3]);
        *reinterpret_cast<float4*>(po + 4) = make_float4(r[4], r[5], r[6], r[7]);
        g_pl[kh][rowid] = ll + lh;
    }
}

// ---------------------------------------------------------------------------
// Combine: sum the 8 key-eighth partials, normalize, scatter to [B,S,E].
// ---------------------------------------------------------------------------
__global__ void __launch_bounds__(256) combine_kernel() {
    int n = blockIdx.x * 256 + threadIdx.x;    // 0..131071

    float r[8] = {0, 0, 0, 0, 0, 0, 0, 0};
    float l = 0.f;
#pragma unroll
    for (int k = 0; k < KH; k++) {
        const float4* p = reinterpret_cast<const float4*>(&g_po[k][n][0]);
        float4 a = p[0], bq = p[1];
        r[0] += a.x;  r[1] += a.y;  r[2] += a.z;  r[3] += a.w;
        r[4] += bq.x; r[5] += bq.y; r[6] += bq.z; r[7] += bq.w;
        l += g_pl[k][n];
    }
    float inv = 1.f / l;

    int bh = n >> 10, sq = n & 1023;
    int b = bh >> 5, h = bh & 31;
    float* dst = g_att + ((size_t)(b * SS + sq)) * EE + h * DD;
    *reinterpret_cast<float4*>(dst) = make_float4(
        r[0] * inv, r[1] * inv, r[2] * inv, r[3] * inv);
    *reinterpret_cast<float4*>(dst + 4) = make_float4(
        r[4] * inv, r[5] * inv, r[6] * inv, r[7] * inv);
}

// ---------------------------------------------------------------------------
// GEMM: out = g_att @ W^T.  M=4096, N=256, K=256, fp32.  (unchanged)
// Tile 64m x 64n, 128 threads, micro 4m x 8n. Full B tile transposed in
// 64 KB dynamic SMEM, ONE sync; A streamed GMEM->regs with k8 prefetch.
// ---------------------------------------------------------------------------
__global__ void __launch_bounds__(128) gemm_kernel(const float* __restrict__ W,
                                                   float* __restrict__ out) {
    extern __shared__ float BsF[];     // 64 KB: BsF[k*64 + n_local]

    int tid = threadIdx.x;
    int tx = tid & 7;
    int ty = tid >> 3;
    int n0 = blockIdx.x * 64, m0 = blockIdx.y * 64;

#pragma unroll
    for (int it = 0; it < 32; it++) {
        int idx = tid + it * 128;
        int r  = idx & 63;
        int c4 = idx >> 6;
        float4 v = *reinterpret_cast<const float4*>(
            &W[(size_t)(n0 + r) * EE + c4 * 4]);
        BsF[(c4 * 4 + 0) * 64 + r] = v.x;
        BsF[(c4 * 4 + 1) * 64 + r] = v.y;
        BsF[(c4 * 4 + 2) * 64 + r] = v.z;
        BsF[(c4 * 4 + 3) * 64 + r] = v.w;
    }
    __syncthreads();

    unsigned long long acc[4][4];
#pragma unroll
    for (int i = 0; i < 4; i++)
#pragma unroll
        for (int j = 0; j < 4; j++) acc[i][j] = 0ULL;

    const float* gA[4];
#pragma unroll
    for (int i = 0; i < 4; i++)
        gA[i] = &g_att[(size_t)(m0 + ty * 4 + i) * EE];

    const unsigned long long* Bk = reinterpret_cast<const unsigned long long*>(BsF);

    float4 cur[4][2];
#pragma unroll
    for (int i = 0; i < 4; i++) {
        cur[i][0] = *reinterpret_cast<const float4*>(gA[i] + 0);
        cur[i][1] = *reinterpret_cast<const float4*>(gA[i] + 4);
    }

    for (int k8 = 0; k8 < EE; k8 += 8) {
        float4 nxt[4][2];
        if (k8 + 8 < EE) {
#pragma unroll
            for (int i = 0; i < 4; i++) {
                nxt[i][0] = *reinterpret_cast<const float4*>(gA[i] + k8 + 8);
                nxt[i][1] = *reinterpret_cast<const float4*>(gA[i] + k8 + 12);
            }
        }

#pragma unroll
        for (int q = 0; q < 2; q++) {
#pragma unroll
            for (int kk = 0; kk < 4; kk++) {
                int k = k8 + q * 4 + kk;
                unsigned long long b0 = Bk[k * 32 + tx];
                unsigned long long b1 = Bk[k * 32 + tx + 8];
                unsigned long long b2 = Bk[k * 32 + tx + 16];
                unsigned long long b3 = Bk[k * 32 + tx + 24];
#pragma unroll
                for (int i = 0; i < 4; i++) {
                    float av = (kk == 0) ? cur[i][q].x :
                               (kk == 1) ? cur[i][q].y :
                               (kk == 2) ? cur[i][q].z : cur[i][q].w;
                    unsigned long long ad = pack2(av, av);
                    acc[i][0] = ffma2(ad, b0, acc[i][0]);
                    acc[i][1] = ffma2(ad, b1, acc[i][1]);
                    acc[i][2] = ffma2(ad, b2, acc[i][2]);
                    acc[i][3] = ffma2(ad, b3, acc[i][3]);
                }
            }
        }

        if (k8 + 8 < EE) {
#pragma unroll
            for (int i = 0; i < 4; i++) {
                cur[i][0] = nxt[i][0];
                cur[i][1] = nxt[i][1];
            }
        }
    }

#pragma unroll
    for (int i = 0; i < 4; i++) {
        float* row = &out[(size_t)(m0 + ty * 4 + i) * EE + n0];
#pragma unroll
        for (int j = 0; j < 4; j++) {
            float lo, hi;
            unpack2(acc[i][j], lo, hi);
            *reinterpret_cast<float2*>(row + 2 * tx + 16 * j) = make_float2(lo, hi);
        }
    }
}

// ---------------------------------------------------------------------------
constexpr int GEMM_SMEM = 64 * EE * 4;   // 65536 bytes

extern "C" void kernel_launch(void* const* d_in, const int* in_sizes, int n_in,
                              void* d_out, int out_size) {
    const float* x = nullptr;
    const float* theta = nullptr;
    const float* w = nullptr;
    for (int i = 0; i < n_in; i++) {
        if (in_sizes[i] == NROWS * DD)      x = (const float*)d_in[i];
        else if (in_sizes[i] == DD)         theta = (const float*)d_in[i];
        else if (in_sizes[i] == EE * EE)    w = (const float*)d_in[i];
    }

    // Host-side attribute set: graph-capture-safe, deterministic.
    cudaFuncSetAttribute(gemm_kernel,
                         cudaFuncAttributeMaxDynamicSharedMemorySize, GEMM_SMEM);

    attn_kernel<<<dim3(BB * HH, 4, KH), 128>>>(x, theta);
    combine_kernel<<<NQ / 256, 256>>>();
    gemm_kernel<<<dim3(EE / 64, BB * SS / 64), 128, GEMM_SMEM>>>(w, (float*)d_out);
}

// round 15
// speedup vs baseline: 1.0362x; 1.0362x over previous
#include <cuda_runtime.h>
#include <cstdint>

#define BB 4
#define SS 1024
#define HH 32
#define DD 8
#define EE 256
#define KH 4                                   // split-K factor
#define KT (SS / KH)                           // 256 keys per tile
constexpr int NROWS = BB * SS * HH;            // 131072
constexpr int NQ = BB * HH * SS;               // 131072 (rows x heads)

// Scratch (allocation-free rule: __device__ globals)
__device__ float g_att[BB * SS * EE];          // [B,S,E] attention out, 4 MB
__device__ float g_po[KH][NQ][8];              // split-K partial o, 16.8 MB
__device__ float g_pl[KH][NQ];                 // split-K partial l, 2 MB

// ---------- packed f32x2 helpers (Blackwell dual FP32 datapath) ----------
__device__ __forceinline__ unsigned long long pack2(float lo, float hi) {
    unsigned long long r;
    asm("mov.b64 %0, {%1, %2};" : "=l"(r) : "f"(lo), "f"(hi));
    return r;
}
__device__ __forceinline__ void unpack2(unsigned long long v, float& lo, float& hi) {
    asm("mov.b64 {%0, %1}, %2;" : "=f"(lo), "=f"(hi) : "l"(v));
}
__device__ __forceinline__ unsigned long long ffma2(unsigned long long a,
                                                    unsigned long long b,
                                                    unsigned long long c) {
    unsigned long long d;
    asm("fma.rn.f32x2 %0, %1, %2, %3;" : "=l"(d) : "l"(a), "l"(b), "l"(c));
    return d;
}
__device__ __forceinline__ unsigned long long fadd2(unsigned long long a,
                                                    unsigned long long b) {
    unsigned long long d;
    asm("add.rn.f32x2 %0, %1, %2;" : "=l"(d) : "l"(a), "l"(b));
    return d;
}
__device__ __forceinline__ float ex2(float x) {
    float y;
    asm("ex2.approx.ftz.f32 %0, %1;" : "=f"(y) : "f"(x));
    return y;
}

// closed-form circuit row: z[w] = prod_{j<=w} cos(x_j+th_j) (w>=1),
// z[0] = prod_{1..7} cos(x_j+th_j)
__device__ __forceinline__ void circuit_row(const float* xr, const float* th,
                                            float* z) {
    float4 xa = reinterpret_cast<const float4*>(xr)[0];
    float4 xb = reinterpret_cast<const float4*>(xr)[1];
    float c[8];
    c[0] = cosf(xa.x + th[0]); c[1] = cosf(xa.y + th[1]);
    c[2] = cosf(xa.z + th[2]); c[3] = cosf(xa.w + th[3]);
    c[4] = cosf(xb.x + th[4]); c[5] = cosf(xb.y + th[5]);
    c[6] = cosf(xb.z + th[6]); c[7] = cosf(xb.w + th[7]);
    float p = c[0];
#pragma unroll
    for (int w = 1; w < 8; w++) { p *= c[w]; z[w] = p; }
    float s = c[7];
#pragma unroll
    for (int w = 6; w >= 1; w--) s *= c[w];
    z[0] = s;
}

// ---------------------------------------------------------------------------
// Attention, split-K(4) + 4 QUERIES/THREAD.  LDS.128 per key-pair is now
// amortized over 4 score+AV chains: LDS crossbar demand ~32us << FMA ~72us,
// and 4 independent chains cover the FFMA/ex2 latencies.
// Grid (128 heads, 2 q-slabs, 4 key-quarters) x 128 threads = 1024 blocks.
// Phase 1: 256-key tile, pair-packed sF[p*16 + 2d + lane] (8 KB), 2 rows/thr.
// Phase 2: one key-pair load (4 x LDS.128) -> 4 score chains -> ex2/lane ->
// 4 x 8 AV ffma2. |score| <= sqrt(8): no max subtraction.
// Unnormalized partials (sum p*K, sum p) out; combine kernel reduces.
// ---------------------------------------------------------------------------
__global__ void __launch_bounds__(128) attn_kernel(const float* __restrict__ x,
                                                   const float* __restrict__ theta) {
    __shared__ float sF[KT * 8];    // 8 KB pair-packed key tile

    int bh   = blockIdx.x;          // 0..127 (b*32 + h)
    int slab = blockIdx.y;          // 0..1 (512 queries each)
    int kh   = blockIdx.z;          // 0..3 key quarter
    int tid  = threadIdx.x;
    int b = bh >> 5, h = bh & 31;

    float th[8];
#pragma unroll
    for (int d = 0; d < 8; d++) th[d] = theta[d];

    // Phase 1: key tile (256 rows, 2 per thread)
#pragma unroll
    for (int it = 0; it < 2; it++) {
        int j = tid + it * 128;
        int row = kh * KT + j;
        float z[8];
        circuit_row(x + ((size_t)(b * SS + row) * EE + h * DD), th, z);
        int base = (j >> 1) * 16 + (j & 1);
#pragma unroll
        for (int d = 0; d < 8; d++) sF[base + 2 * d] = z[d];
    }

    // This thread's FOUR query rows, closed-form from x, scale folded.
    const float kS = 1.4426950408889634f / 2.8284271247461903f;  // log2(e)/sqrt(8)
    int q0 = slab * 512 + tid * 4;
    unsigned long long q2[4][8];
#pragma unroll
    for (int qi = 0; qi < 4; qi++) {
        float z[8];
        circuit_row(x + ((size_t)(b * SS + q0 + qi) * EE + h * DD), th, z);
#pragma unroll
        for (int d = 0; d < 8; d++) {
            float qv = z[d] * kS;
            q2[qi][d] = pack2(qv, qv);
        }
    }
    __syncthreads();

    unsigned long long o[4][8];
#pragma unroll
    for (int qi = 0; qi < 4; qi++)
#pragma unroll
        for (int d = 0; d < 8; d++) o[qi][d] = 0ULL;
    unsigned long long l2[4] = {0ULL, 0ULL, 0ULL, 0ULL};

    const ulonglong2* kp2 = reinterpret_cast<const ulonglong2*>(sF);

    for (int p = 0; p < KT / 2; p++) {
        // one key-pair load (4 x LDS.128), shared by all 4 queries
        ulonglong2 wv0 = kp2[p * 4 + 0];
        ulonglong2 wv1 = kp2[p * 4 + 1];
        ulonglong2 wv2 = kp2[p * 4 + 2];
        ulonglong2 wv3 = kp2[p * 4 + 3];
        unsigned long long wd[8];
        wd[0] = wv0.x; wd[1] = wv0.y; wd[2] = wv1.x; wd[3] = wv1.y;
        wd[4] = wv2.x; wd[5] = wv2.y; wd[6] = wv3.x; wd[7] = wv3.y;

        // 4 independent score chains (ILP-4)
        unsigned long long s[4];
#pragma unroll
        for (int qi = 0; qi < 4; qi++) s[qi] = ffma2(q2[qi][0], wd[0], 0ULL);
#pragma unroll
        for (int d = 1; d < 8; d++)
#pragma unroll
            for (int qi = 0; qi < 4; qi++)
                s[qi] = ffma2(q2[qi][d], wd[d], s[qi]);

        unsigned long long pp[4];
#pragma unroll
        for (int qi = 0; qi < 4; qi++) {
            float a, bq;
            unpack2(s[qi], a, bq);
            pp[qi] = pack2(ex2(a), ex2(bq));
            l2[qi] = fadd2(l2[qi], pp[qi]);
        }

#pragma unroll
        for (int d = 0; d < 8; d++)
#pragma unroll
            for (int qi = 0; qi < 4; qi++)
                o[qi][d] = ffma2(pp[qi], wd[d], o[qi][d]);
    }

#pragma unroll
    for (int qi = 0; qi < 4; qi++) {
        float ll, lh;
        unpack2(l2[qi], ll, lh);

        float r[8];
#pragma unroll
        for (int d = 0; d < 8; d++) {
            float lo, hi;
            unpack2(o[qi][d], lo, hi);
            r[d] = lo + hi;
        }

        int rowid = bh * SS + q0 + qi;
        float* po = &g_po[kh][rowid][0];
        *reinterpret_cast<float4*>(po)     = make_float4(r[0], r[1], r[2], r[3]);
        *reinterpret_cast<float4*>(po + 4) = make_float4(r[4], r[5], r[6], r[7]);
        g_pl[kh][rowid] = ll + lh;
    }
}

// ---------------------------------------------------------------------------
// Combine: sum the 4 key-quarter partials, normalize, scatter to [B,S,E].
// ---------------------------------------------------------------------------
__global__ void __launch_bounds__(256) combine_kernel() {
    int n = blockIdx.x * 256 + threadIdx.x;    // 0..131071

    float r[8] = {0, 0, 0, 0, 0, 0, 0, 0};
    float l = 0.f;
#pragma unroll
    for (int k = 0; k < KH; k++) {
        const float4* p = reinterpret_cast<const float4*>(&g_po[k][n][0]);
        float4 a = p[0], bq = p[1];
        r[0] += a.x;  r[1] += a.y;  r[2] += a.z;  r[3] += a.w;
        r[4] += bq.x; r[5] += bq.y; r[6] += bq.z; r[7] += bq.w;
        l += g_pl[k][n];
    }
    float inv = 1.f / l;

    int bh = n >> 10, sq = n & 1023;
    int b = bh >> 5, h = bh & 31;
    float* dst = g_att + ((size_t)(b * SS + sq)) * EE + h * DD;
    *reinterpret_cast<float4*>(dst) = make_float4(
        r[0] * inv, r[1] * inv, r[2] * inv, r[3] * inv);
    *reinterpret_cast<float4*>(dst + 4) = make_float4(
        r[4] * inv, r[5] * inv, r[6] * inv, r[7] * inv);
}

// ---------------------------------------------------------------------------
// GEMM: out = g_att @ W^T.  M=4096, N=256, K=256, fp32.  (unchanged)
// Tile 64m x 64n, 128 threads, micro 4m x 8n. Full B tile transposed in
// 64 KB dynamic SMEM, ONE sync; A streamed GMEM->regs with k8 prefetch.
// ---------------------------------------------------------------------------
__global__ void __launch_bounds__(128) gemm_kernel(const float* __restrict__ W,
                                                   float* __restrict__ out) {
    extern __shared__ float BsF[];     // 64 KB: BsF[k*64 + n_local]

    int tid = threadIdx.x;
    int tx = tid & 7;
    int ty = tid >> 3;
    int n0 = blockIdx.x * 64, m0 = blockIdx.y * 64;

#pragma unroll
    for (int it = 0; it < 32; it++) {
        int idx = tid + it * 128;
        int r  = idx & 63;
        int c4 = idx >> 6;
        float4 v = *reinterpret_cast<const float4*>(
            &W[(size_t)(n0 + r) * EE + c4 * 4]);
        BsF[(c4 * 4 + 0) * 64 + r] = v.x;
        BsF[(c4 * 4 + 1) * 64 + r] = v.y;
        BsF[(c4 * 4 + 2) * 64 + r] = v.z;
        BsF[(c4 * 4 + 3) * 64 + r] = v.w;
    }
    __syncthreads();

    unsigned long long acc[4][4];
#pragma unroll
    for (int i = 0; i < 4; i++)
#pragma unroll
        for (int j = 0; j < 4; j++) acc[i][j] = 0ULL;

    const float* gA[4];
#pragma unroll
    for (int i = 0; i < 4; i++)
        gA[i] = &g_att[(size_t)(m0 + ty * 4 + i) * EE];

    const unsigned long long* Bk = reinterpret_cast<const unsigned long long*>(BsF);

    float4 cur[4][2];
#pragma unroll
    for (int i = 0; i < 4; i++) {
        cur[i][0] = *reinterpret_cast<const float4*>(gA[i] + 0);
        cur[i][1] = *reinterpret_cast<const float4*>(gA[i] + 4);
    }

    for (int k8 = 0; k8 < EE; k8 += 8) {
        float4 nxt[4][2];
        if (k8 + 8 < EE) {
#pragma unroll
            for (int i = 0; i < 4; i++) {
                nxt[i][0] = *reinterpret_cast<const float4*>(gA[i] + k8 + 8);
                nxt[i][1] = *reinterpret_cast<const float4*>(gA[i] + k8 + 12);
            }
        }

#pragma unroll
        for (int q = 0; q < 2; q++) {
#pragma unroll
            for (int kk = 0; kk < 4; kk++) {
                int k = k8 + q * 4 + kk;
                unsigned long long b0 = Bk[k * 32 + tx];
                unsigned long long b1 = Bk[k * 32 + tx + 8];
                unsigned long long b2 = Bk[k * 32 + tx + 16];
                unsigned long long b3 = Bk[k * 32 + tx + 24];
#pragma unroll
                for (int i = 0; i < 4; i++) {
                    float av = (kk == 0) ? cur[i][q].x :
                               (kk == 1) ? cur[i][q].y :
                               (kk == 2) ? cur[i][q].z : cur[i][q].w;
                    unsigned long long ad = pack2(av, av);
                    acc[i][0] = ffma2(ad, b0, acc[i][0]);
                    acc[i][1] = ffma2(ad, b1, acc[i][1]);
                    acc[i][2] = ffma2(ad, b2, acc[i][2]);
                    acc[i][3] = ffma2(ad, b3, acc[i][3]);
                }
            }
        }

        if (k8 + 8 < EE) {
#pragma unroll
            for (int i = 0; i < 4; i++) {
                cur[i][0] = nxt[i][0];
                cur[i][1] = nxt[i][1];
            }
        }
    }

#pragma unroll
    for (int i = 0; i < 4; i++) {
        float* row = &out[(size_t)(m0 + ty * 4 + i) * EE + n0];
#pragma unroll
        for (int j = 0; j < 4; j++) {
            float lo, hi;
            unpack2(acc[i][j], lo, hi);
            *reinterpret_cast<float2*>(row + 2 * tx + 16 * j) = make_float2(lo, hi);
        }
    }
}

// ---------------------------------------------------------------------------
constexpr int GEMM_SMEM = 64 * EE * 4;   // 65536 bytes

extern "C" void kernel_launch(void* const* d_in, const int* in_sizes, int n_in,
                              void* d_out, int out_size) {
    const float* x = nullptr;
    const float* theta = nullptr;
    const float* w = nullptr;
    for (int i = 0; i < n_in; i++) {
        if (in_sizes[i] == NROWS * DD)      x = (const float*)d_in[i];
        else if (in_sizes[i] == DD)         theta = (const float*)d_in[i];
        else if (in_sizes[i] == EE * EE)    w = (const float*)d_in[i];
    }

    // Host-side attribute set: graph-capture-safe, deterministic.
    cudaFuncSetAttribute(gemm_kernel,
                         cudaFuncAttributeMaxDynamicSharedMemorySize, GEMM_SMEM);

    attn_kernel<<<dim3(BB * HH, 2, KH), 128>>>(x, theta);
    combine_kernel<<<NQ / 256, 256>>>();
    gemm_kernel<<<dim3(EE / 64, BB * SS / 64), 128, GEMM_SMEM>>>(w, (float*)d_out);
}

// round 16
// speedup vs baseline: 1.3175x; 1.2715x over previous
#include <cuda_runtime.h>
#include <cstdint>

#define BB 4
#define SS 1024
#define HH 32
#define DD 8
#define EE 256
constexpr int NROWS = BB * SS * HH;            // 131072

// Scratch (allocation-free rule: __device__ globals)
__device__ float g_att[BB * SS * EE];          // [B,S,E] attention out, 4 MB

// ---------- helpers ----------
__device__ __forceinline__ float ex2f(float x) {
    float y;
    asm("ex2.approx.ftz.f32 %0, %1;" : "=f"(y) : "f"(x));
    return y;
}
// pack two fp32 -> bf16x2 (lo element in low half)
__device__ __forceinline__ uint32_t cvt2bf(float lo, float hi) {
    uint32_t r;
    asm("cvt.rn.satfinite.bf16x2.f32 %0, %1, %2;" : "=r"(r) : "f"(hi), "f"(lo));
    return r;
}
__device__ __forceinline__ float bflo(uint32_t w) { return __uint_as_float(w << 16); }
__device__ __forceinline__ float bfhi(uint32_t w) { return __uint_as_float(w & 0xffff0000u); }

// warp MMA: D(16x8,f32) += A(16x8,bf16,row) * B(8x8,bf16,col)
__device__ __forceinline__ void mma8(float* c, uint32_t a0, uint32_t a1, uint32_t b0) {
    asm volatile(
        "mma.sync.aligned.m16n8k8.row.col.f32.bf16.bf16.f32 "
        "{%0,%1,%2,%3}, {%4,%5}, {%6}, {%0,%1,%2,%3};"
        : "+f"(c[0]), "+f"(c[1]), "+f"(c[2]), "+f"(c[3])
        : "r"(a0), "r"(a1), "r"(b0));
}
// warp MMA: D(16x8,f32) += A(16x16,bf16,row) * B(16x8,bf16,col)
__device__ __forceinline__ void mma16(float* c, const uint32_t* a, uint32_t b0, uint32_t b1) {
    asm volatile(
        "mma.sync.aligned.m16n8k16.row.col.f32.bf16.bf16.f32 "
        "{%0,%1,%2,%3}, {%4,%5,%6,%7}, {%8,%9}, {%0,%1,%2,%3};"
        : "+f"(c[0]), "+f"(c[1]), "+f"(c[2]), "+f"(c[3])
        : "r"(a[0]), "r"(a[1]), "r"(a[2]), "r"(a[3]), "r"(b0), "r"(b1));
}

// closed-form circuit row: z[w] = prod_{j<=w} cos(x_j+th_j) (w>=1),
// z[0] = prod_{1..7} cos(x_j+th_j)
__device__ __forceinline__ void circuit_row(const float* xr, const float* th, float* z) {
    float4 xa = reinterpret_cast<const float4*>(xr)[0];
    float4 xb = reinterpret_cast<const float4*>(xr)[1];
    float c[8];
    c[0] = cosf(xa.x + th[0]); c[1] = cosf(xa.y + th[1]);
    c[2] = cosf(xa.z + th[2]); c[3] = cosf(xa.w + th[3]);
    c[4] = cosf(xb.x + th[4]); c[5] = cosf(xb.y + th[5]);
    c[6] = cosf(xb.z + th[6]); c[7] = cosf(xb.w + th[7]);
    float p = c[0];
#pragma unroll
    for (int w = 1; w < 8; w++) { p *= c[w]; z[w] = p; }
    float s = c[7];
#pragma unroll
    for (int w = 6; w >= 1; w--) s *= c[w];
    z[0] = s;
}

// ---------------------------------------------------------------------------
// Tensor-core flash attention (warp mma.sync, bf16 hi/lo error compensation).
// CTA = (head, 128-q slab), 4 warps; warp owns 32 q rows (2 m16 tiles).
// 8 chunks of 128 keys, generated closed-form into SMEM each iteration:
//   sKh/sKl: K rows [128][8] bf16 (B operand of S-mma)
//   sVh/sVl: V^T [8][128] bf16, row stride 136 halfwords (conflict-free)
// Per 16-key step: S tiles via 3 split m16n8k8 mmas; ex2 on C regs;
// C->A fragment identity converts P (2 cvt per 4 elems); O += 3 split
// m16n8k16 mmas, accumulated in C regs across all 1024 keys (no max
// subtraction needed since |S| <= sqrt(8)*log2e). l per-row in regs,
// quad-shuffle reduced at the end.
// ---------------------------------------------------------------------------
__global__ void __launch_bounds__(128) attn_kernel(const float* __restrict__ x,
                                                   const float* __restrict__ theta) {
    __shared__ uint32_t sQh[512], sQl[512];        // Q rows [128][4] words
    __shared__ uint32_t sKh[512], sKl[512];        // K chunk rows [128][4] words
    __shared__ uint32_t sVh[8 * 68], sVl[8 * 68];  // V^T padded, 68 words/row

    int tid = threadIdx.x;
    int w   = tid >> 5;
    int ln  = tid & 31;
    int g   = ln >> 2;        // 0..7
    int qc  = ln & 3;         // 0..3
    int bh = blockIdx.x, slab = blockIdx.y;
    int b = bh >> 5, h = bh & 31;

    float th[8];
#pragma unroll
    for (int d = 0; d < 8; d++) th[d] = theta[d];

    const float kS = 1.4426950408889634f / 2.8284271247461903f;  // log2(e)/sqrt(8)

    // ---- generate Q rows (1/thread), scale folded, bf16 hi/lo split ----
    {
        float z[8];
        circuit_row(x + ((size_t)(b * SS + slab * 128 + tid) * EE + h * DD), th, z);
#pragma unroll
        for (int d2 = 0; d2 < 4; d2++) {
            float a = z[2 * d2] * kS, cc = z[2 * d2 + 1] * kS;
            uint32_t hw = cvt2bf(a, cc);
            uint32_t lw = cvt2bf(a - bflo(hw), cc - bfhi(hw));
            sQh[tid * 4 + d2] = hw;
            sQl[tid * 4 + d2] = lw;
        }
    }
    __syncthreads();

    // ---- load persistent Q A-fragments (2 m-tiles x hi/lo) ----
    uint32_t aQh[2][2], aQl[2][2];
#pragma unroll
    for (int mt = 0; mt < 2; mt++) {
        int rb = w * 32 + mt * 16;
        aQh[mt][0] = sQh[(rb + g) * 4 + qc];
        aQh[mt][1] = sQh[(rb + 8 + g) * 4 + qc];
        aQl[mt][0] = sQl[(rb + g) * 4 + qc];
        aQl[mt][1] = sQl[(rb + 8 + g) * 4 + qc];
    }

    float oc[2][4] = {{0, 0, 0, 0}, {0, 0, 0, 0}};   // O accumulators (f32)
    float ls[2][2] = {{0, 0}, {0, 0}};                // row-sum partials

    for (int c = 0; c < 8; c++) {
        // generate this thread's key row into regs (before barrier)
        float z[8];
        circuit_row(x + ((size_t)(b * SS + c * 128 + tid) * EE + h * DD), th, z);
        uint32_t khw[4], klw[4];
#pragma unroll
        for (int d2 = 0; d2 < 4; d2++) {
            float a = z[2 * d2], cc = z[2 * d2 + 1];
            khw[d2] = cvt2bf(a, cc);
            klw[d2] = cvt2bf(a - bflo(khw[d2]), cc - bfhi(khw[d2]));
        }
        __syncthreads();   // previous chunk fully consumed
        reinterpret_cast<uint4*>(sKh)[tid] = make_uint4(khw[0], khw[1], khw[2], khw[3]);
        reinterpret_cast<uint4*>(sKl)[tid] = make_uint4(klw[0], klw[1], klw[2], klw[3]);
        {
            uint16_t* vh16 = reinterpret_cast<uint16_t*>(sVh);
            uint16_t* vl16 = reinterpret_cast<uint16_t*>(sVl);
#pragma unroll
            for (int d = 0; d < 8; d++) {
                uint16_t hh = (d & 1) ? (uint16_t)(khw[d >> 1] >> 16)
                                      : (uint16_t)(khw[d >> 1] & 0xffffu);
                uint16_t l2 = (d & 1) ? (uint16_t)(klw[d >> 1] >> 16)
                                      : (uint16_t)(klw[d >> 1] & 0xffffu);
                vh16[d * 136 + tid] = hh;
                vl16[d * 136 + tid] = l2;
            }
        }
        __syncthreads();   // chunk visible

#pragma unroll 2
        for (int s = 0; s < 8; s++) {            // 16 keys per step
            uint32_t bh0 = sKh[(s * 16 + g) * 4 + qc];
            uint32_t bh1 = sKh[(s * 16 + 8 + g) * 4 + qc];
            uint32_t bl0 = sKl[(s * 16 + g) * 4 + qc];
            uint32_t bl1 = sKl[(s * 16 + 8 + g) * 4 + qc];
            int vw = g * 68 + s * 8 + qc;
            uint32_t vh0 = sVh[vw], vh1 = sVh[vw + 4];
            uint32_t vl0 = sVl[vw], vl1 = sVl[vw + 4];

#pragma unroll
            for (int mt = 0; mt < 2; mt++) {
                float c0[4] = {0, 0, 0, 0}, c1[4] = {0, 0, 0, 0};
                mma8(c0, aQh[mt][0], aQh[mt][1], bh0);
                mma8(c0, aQl[mt][0], aQl[mt][1], bh0);
                mma8(c0, aQh[mt][0], aQh[mt][1], bl0);
                mma8(c1, aQh[mt][0], aQh[mt][1], bh1);
                mma8(c1, aQl[mt][0], aQl[mt][1], bh1);
                mma8(c1, aQh[mt][0], aQh[mt][1], bl1);

                float e0 = ex2f(c0[0]), e1 = ex2f(c0[1]);
                float e2 = ex2f(c0[2]), e3 = ex2f(c0[3]);
                float e4 = ex2f(c1[0]), e5 = ex2f(c1[1]);
                float e6 = ex2f(c1[2]), e7 = ex2f(c1[3]);
                ls[mt][0] += (e0 + e1) + (e4 + e5);   // row g
                ls[mt][1] += (e2 + e3) + (e6 + e7);   // row g+8

                uint32_t ah[4], al[4];
                ah[0] = cvt2bf(e0, e1);
                ah[1] = cvt2bf(e2, e3);
                ah[2] = cvt2bf(e4, e5);
                ah[3] = cvt2bf(e6, e7);
                al[0] = cvt2bf(e0 - bflo(ah[0]), e1 - bfhi(ah[0]));
                al[1] = cvt2bf(e2 - bflo(ah[1]), e3 - bfhi(ah[1]));
                al[2] = cvt2bf(e4 - bflo(ah[2]), e5 - bfhi(ah[2]));
                al[3] = cvt2bf(e6 - bflo(ah[3]), e7 - bfhi(ah[3]));

                mma16(oc[mt], ah, vh0, vh1);
                mma16(oc[mt], al, vh0, vh1);
                mma16(oc[mt], ah, vl0, vl1);
            }
        }
    }

    // ---- reduce row sums across quads, normalize, write ----
#pragma unroll
    for (int mt = 0; mt < 2; mt++) {
        float l0 = ls[mt][0], l1 = ls[mt][1];
        l0 += __shfl_xor_sync(0xffffffffu, l0, 1);
        l0 += __shfl_xor_sync(0xffffffffu, l0, 2);
        l1 += __shfl_xor_sync(0xffffffffu, l1, 1);
        l1 += __shfl_xor_sync(0xffffffffu, l1, 2);
        float i0 = 1.f / l0, i1 = 1.f / l1;
        int rb = slab * 128 + w * 32 + mt * 16;
        float* d0 = g_att + ((size_t)(b * SS + rb + g)) * EE + h * DD + 2 * qc;
        float* d1 = g_att + ((size_t)(b * SS + rb + 8 + g)) * EE + h * DD + 2 * qc;
        *reinterpret_cast<float2*>(d0) = make_float2(oc[mt][0] * i0, oc[mt][1] * i0);
        *reinterpret_cast<float2*>(d1) = make_float2(oc[mt][2] * i1, oc[mt][3] * i1);
    }
}

// ---------- packed f32x2 helpers for the gemm ----------
__device__ __forceinline__ unsigned long long pack2(float lo, float hi) {
    unsigned long long r;
    asm("mov.b64 %0, {%1, %2};" : "=l"(r) : "f"(lo), "f"(hi));
    return r;
}
__device__ __forceinline__ void unpack2(unsigned long long v, float& lo, float& hi) {
    asm("mov.b64 {%0, %1}, %2;" : "=f"(lo), "=f"(hi) : "l"(v));
}
__device__ __forceinline__ unsigned long long ffma2(unsigned long long a,
                                                    unsigned long long b,
                                                    unsigned long long c) {
    unsigned long long d;
    asm("fma.rn.f32x2 %0, %1, %2, %3;" : "=l"(d) : "l"(a), "l"(b), "l"(c));
    return d;
}

// ---------------------------------------------------------------------------
// GEMM: out = g_att @ W^T.  M=4096, N=256, K=256, fp32.  (unchanged)
// ---------------------------------------------------------------------------
__global__ void __launch_bounds__(128) gemm_kernel(const float* __restrict__ W,
                                                   float* __restrict__ out) {
    extern __shared__ float BsF[];     // 64 KB: BsF[k*64 + n_local]

    int tid = threadIdx.x;
    int tx = tid & 7;
    int ty = tid >> 3;
    int n0 = blockIdx.x * 64, m0 = blockIdx.y * 64;

#pragma unroll
    for (int it = 0; it < 32; it++) {
        int idx = tid + it * 128;
        int r  = idx & 63;
        int c4 = idx >> 6;
        float4 v = *reinterpret_cast<const float4*>(
            &W[(size_t)(n0 + r) * EE + c4 * 4]);
        BsF[(c4 * 4 + 0) * 64 + r] = v.x;
        BsF[(c4 * 4 + 1) * 64 + r] = v.y;
        BsF[(c4 * 4 + 2) * 64 + r] = v.z;
        BsF[(c4 * 4 + 3) * 64 + r] = v.w;
    }
    __syncthreads();

    unsigned long long acc[4][4];
#pragma unroll
    for (int i = 0; i < 4; i++)
#pragma unroll
        for (int j = 0; j < 4; j++) acc[i][j] = 0ULL;

    const float* gA[4];
#pragma unroll
    for (int i = 0; i < 4; i++)
        gA[i] = &g_att[(size_t)(m0 + ty * 4 + i) * EE];

    const unsigned long long* Bk = reinterpret_cast<const unsigned long long*>(BsF);

    float4 cur[4][2];
#pragma unroll
    for (int i = 0; i < 4; i++) {
        cur[i][0] = *reinterpret_cast<const float4*>(gA[i] + 0);
        cur[i][1] = *reinterpret_cast<const float4*>(gA[i] + 4);
    }

    for (int k8 = 0; k8 < EE; k8 += 8) {
        float4 nxt[4][2];
        if (k8 + 8 < EE) {
#pragma unroll
            for (int i = 0; i < 4; i++) {
                nxt[i][0] = *reinterpret_cast<const float4*>(gA[i] + k8 + 8);
                nxt[i][1] = *reinterpret_cast<const float4*>(gA[i] + k8 + 12);
            }
        }

#pragma unroll
        for (int q = 0; q < 2; q++) {
#pragma unroll
            for (int kk = 0; kk < 4; kk++) {
                int k = k8 + q * 4 + kk;
                unsigned long long b0 = Bk[k * 32 + tx];
                unsigned long long b1 = Bk[k * 32 + tx + 8];
                unsigned long long b2 = Bk[k * 32 + tx + 16];
                unsigned long long b3 = Bk[k * 32 + tx + 24];
#pragma unroll
                for (int i = 0; i < 4; i++) {
                    float av = (kk == 0) ? cur[i][q].x :
                               (kk == 1) ? cur[i][q].y :
                               (kk == 2) ? cur[i][q].z : cur[i][q].w;
                    unsigned long long ad = pack2(av, av);
                    acc[i][0] = ffma2(ad, b0, acc[i][0]);
                    acc[i][1] = ffma2(ad, b1, acc[i][1]);
                    acc[i][2] = ffma2(ad, b2, acc[i][2]);
                    acc[i][3] = ffma2(ad, b3, acc[i][3]);
                }
            }
        }

        if (k8 + 8 < EE) {
#pragma unroll
            for (int i = 0; i < 4; i++) {
                cur[i][0] = nxt[i][0];
                cur[i][1] = nxt[i][1];
            }
        }
    }

#pragma unroll
    for (int i = 0; i < 4; i++) {
        float* row = &out[(size_t)(m0 + ty * 4 + i) * EE + n0];
#pragma unroll
        for (int j = 0; j < 4; j++) {
            float lo, hi;
            unpack2(acc[i][j], lo, hi);
            *reinterpret_cast<float2*>(row + 2 * tx + 16 * j) = make_float2(lo, hi);
        }
    }
}

// ---------------------------------------------------------------------------
constexpr int GEMM_SMEM = 64 * EE * 4;   // 65536 bytes

extern "C" void kernel_launch(void* const* d_in, const int* in_sizes, int n_in,
                              void* d_out, int out_size) {
    const float* x = nullptr;
    const float* theta = nullptr;
    const float* w = nullptr;
    for (int i = 0; i < n_in; i++) {
        if (in_sizes[i] == NROWS * DD)      x = (const float*)d_in[i];
        else if (in_sizes[i] == DD)         theta = (const float*)d_in[i];
        else if (in_sizes[i] == EE * EE)    w = (const float*)d_in[i];
    }

    // Host-side attribute set: graph-capture-safe, deterministic.
    cudaFuncSetAttribute(gemm_kernel,
                         cudaFuncAttributeMaxDynamicSharedMemorySize, GEMM_SMEM);

    attn_kernel<<<dim3(BB * HH, 8), 128>>>(x, theta);
    gemm_kernel<<<dim3(EE / 64, BB * SS / 64), 128, GEMM_SMEM>>>(w, (float*)d_out);
}

// round 17
// speedup vs baseline: 1.4634x; 1.1108x over previous
#include <cuda_runtime.h>
#include <cstdint>

#define BB 4
#define SS 1024
#define HH 32
#define DD 8
#define EE 256
constexpr int NROWS = BB * SS * HH;            // 131072

// Scratch (allocation-free rule: __device__ globals)
__device__ float g_att[BB * SS * EE];          // [B,S,E] attention out, 4 MB

// ---------- helpers ----------
__device__ __forceinline__ float ex2f(float x) {
    float y;
    asm("ex2.approx.ftz.f32 %0, %1;" : "=f"(y) : "f"(x));
    return y;
}
// pack two fp32 -> bf16x2 (lo element in low half)
__device__ __forceinline__ uint32_t cvt2bf(float lo, float hi) {
    uint32_t r;
    asm("cvt.rn.satfinite.bf16x2.f32 %0, %1, %2;" : "=r"(r) : "f"(hi), "f"(lo));
    return r;
}
__device__ __forceinline__ float bflo(uint32_t w) { return __uint_as_float(w << 16); }
__device__ __forceinline__ float bfhi(uint32_t w) { return __uint_as_float(w & 0xffff0000u); }

// warp MMA: D(16x8,f32) += A(16x8,bf16,row) * B(8x8,bf16,col)
__device__ __forceinline__ void mma8(float* c, uint32_t a0, uint32_t a1, uint32_t b0) {
    asm volatile(
        "mma.sync.aligned.m16n8k8.row.col.f32.bf16.bf16.f32 "
        "{%0,%1,%2,%3}, {%4,%5}, {%6}, {%0,%1,%2,%3};"
        : "+f"(c[0]), "+f"(c[1]), "+f"(c[2]), "+f"(c[3])
        : "r"(a0), "r"(a1), "r"(b0));
}
// warp MMA: D(16x8,f32) += A(16x16,bf16,row) * B(16x8,bf16,col)
__device__ __forceinline__ void mma16(float* c, const uint32_t* a, uint32_t b0, uint32_t b1) {
    asm volatile(
        "mma.sync.aligned.m16n8k16.row.col.f32.bf16.bf16.f32 "
        "{%0,%1,%2,%3}, {%4,%5,%6,%7}, {%8,%9}, {%0,%1,%2,%3};"
        : "+f"(c[0]), "+f"(c[1]), "+f"(c[2]), "+f"(c[3])
        : "r"(a[0]), "r"(a[1]), "r"(a[2]), "r"(a[3]), "r"(b0), "r"(b1));
}

// closed-form circuit row: z[w] = prod_{j<=w} cos(x_j+th_j) (w>=1),
// z[0] = prod_{1..7} cos(x_j+th_j)
__device__ __forceinline__ void circuit_row(const float* xr, const float* th, float* z) {
    float4 xa = reinterpret_cast<const float4*>(xr)[0];
    float4 xb = reinterpret_cast<const float4*>(xr)[1];
    float c[8];
    c[0] = cosf(xa.x + th[0]); c[1] = cosf(xa.y + th[1]);
    c[2] = cosf(xa.z + th[2]); c[3] = cosf(xa.w + th[3]);
    c[4] = cosf(xb.x + th[4]); c[5] = cosf(xb.y + th[5]);
    c[6] = cosf(xb.z + th[6]); c[7] = cosf(xb.w + th[7]);
    float p = c[0];
#pragma unroll
    for (int w = 1; w < 8; w++) { p *= c[w]; z[w] = p; }
    float s = c[7];
#pragma unroll
    for (int w = 6; w >= 1; w--) s *= c[w];
    z[0] = s;
}

// ---------------------------------------------------------------------------
// Tensor-core flash attention (UNCHANGED from R16 — verified, ~74us).
// ---------------------------------------------------------------------------
__global__ void __launch_bounds__(128) attn_kernel(const float* __restrict__ x,
                                                   const float* __restrict__ theta) {
    __shared__ uint32_t sQh[512], sQl[512];        // Q rows [128][4] words
    __shared__ uint32_t sKh[512], sKl[512];        // K chunk rows [128][4] words
    __shared__ uint32_t sVh[8 * 68], sVl[8 * 68];  // V^T padded, 68 words/row

    int tid = threadIdx.x;
    int w   = tid >> 5;
    int ln  = tid & 31;
    int g   = ln >> 2;        // 0..7
    int qc  = ln & 3;         // 0..3
    int bh = blockIdx.x, slab = blockIdx.y;
    int b = bh >> 5, h = bh & 31;

    float th[8];
#pragma unroll
    for (int d = 0; d < 8; d++) th[d] = theta[d];

    const float kS = 1.4426950408889634f / 2.8284271247461903f;  // log2(e)/sqrt(8)

    // ---- generate Q rows (1/thread), scale folded, bf16 hi/lo split ----
    {
        float z[8];
        circuit_row(x + ((size_t)(b * SS + slab * 128 + tid) * EE + h * DD), th, z);
#pragma unroll
        for (int d2 = 0; d2 < 4; d2++) {
            float a = z[2 * d2] * kS, cc = z[2 * d2 + 1] * kS;
            uint32_t hw = cvt2bf(a, cc);
            uint32_t lw = cvt2bf(a - bflo(hw), cc - bfhi(hw));
            sQh[tid * 4 + d2] = hw;
            sQl[tid * 4 + d2] = lw;
        }
    }
    __syncthreads();

    // ---- load persistent Q A-fragments (2 m-tiles x hi/lo) ----
    uint32_t aQh[2][2], aQl[2][2];
#pragma unroll
    for (int mt = 0; mt < 2; mt++) {
        int rb = w * 32 + mt * 16;
        aQh[mt][0] = sQh[(rb + g) * 4 + qc];
        aQh[mt][1] = sQh[(rb + 8 + g) * 4 + qc];
        aQl[mt][0] = sQl[(rb + g) * 4 + qc];
        aQl[mt][1] = sQl[(rb + 8 + g) * 4 + qc];
    }

    float oc[2][4] = {{0, 0, 0, 0}, {0, 0, 0, 0}};   // O accumulators (f32)
    float ls[2][2] = {{0, 0}, {0, 0}};                // row-sum partials

    for (int c = 0; c < 8; c++) {
        // generate this thread's key row into regs (before barrier)
        float z[8];
        circuit_row(x + ((size_t)(b * SS + c * 128 + tid) * EE + h * DD), th, z);
        uint32_t khw[4], klw[4];
#pragma unroll
        for (int d2 = 0; d2 < 4; d2++) {
            float a = z[2 * d2], cc = z[2 * d2 + 1];
            khw[d2] = cvt2bf(a, cc);
            klw[d2] = cvt2bf(a - bflo(khw[d2]), cc - bfhi(khw[d2]));
        }
        __syncthreads();   // previous chunk fully consumed
        reinterpret_cast<uint4*>(sKh)[tid] = make_uint4(khw[0], khw[1], khw[2], khw[3]);
        reinterpret_cast<uint4*>(sKl)[tid] = make_uint4(klw[0], klw[1], klw[2], klw[3]);
        {
            uint16_t* vh16 = reinterpret_cast<uint16_t*>(sVh);
            uint16_t* vl16 = reinterpret_cast<uint16_t*>(sVl);
#pragma unroll
            for (int d = 0; d < 8; d++) {
                uint16_t hh = (d & 1) ? (uint16_t)(khw[d >> 1] >> 16)
                                      : (uint16_t)(khw[d >> 1] & 0xffffu);
                uint16_t l2 = (d & 1) ? (uint16_t)(klw[d >> 1] >> 16)
                                      : (uint16_t)(klw[d >> 1] & 0xffffu);
                vh16[d * 136 + tid] = hh;
                vl16[d * 136 + tid] = l2;
            }
        }
        __syncthreads();   // chunk visible

#pragma unroll 2
        for (int s = 0; s < 8; s++) {            // 16 keys per step
            uint32_t bh0 = sKh[(s * 16 + g) * 4 + qc];
            uint32_t bh1 = sKh[(s * 16 + 8 + g) * 4 + qc];
            uint32_t bl0 = sKl[(s * 16 + g) * 4 + qc];
            uint32_t bl1 = sKl[(s * 16 + 8 + g) * 4 + qc];
            int vw = g * 68 + s * 8 + qc;
            uint32_t vh0 = sVh[vw], vh1 = sVh[vw + 4];
            uint32_t vl0 = sVl[vw], vl1 = sVl[vw + 4];

#pragma unroll
            for (int mt = 0; mt < 2; mt++) {
                float c0[4] = {0, 0, 0, 0}, c1[4] = {0, 0, 0, 0};
                mma8(c0, aQh[mt][0], aQh[mt][1], bh0);
                mma8(c0, aQl[mt][0], aQl[mt][1], bh0);
                mma8(c0, aQh[mt][0], aQh[mt][1], bl0);
                mma8(c1, aQh[mt][0], aQh[mt][1], bh1);
                mma8(c1, aQl[mt][0], aQl[mt][1], bh1);
                mma8(c1, aQh[mt][0], aQh[mt][1], bl1);

                float e0 = ex2f(c0[0]), e1 = ex2f(c0[1]);
                float e2 = ex2f(c0[2]), e3 = ex2f(c0[3]);
                float e4 = ex2f(c1[0]), e5 = ex2f(c1[1]);
                float e6 = ex2f(c1[2]), e7 = ex2f(c1[3]);
                ls[mt][0] += (e0 + e1) + (e4 + e5);   // row g
                ls[mt][1] += (e2 + e3) + (e6 + e7);   // row g+8

                uint32_t ah[4], al[4];
                ah[0] = cvt2bf(e0, e1);
                ah[1] = cvt2bf(e2, e3);
                ah[2] = cvt2bf(e4, e5);
                ah[3] = cvt2bf(e6, e7);
                al[0] = cvt2bf(e0 - bflo(ah[0]), e1 - bfhi(ah[0]));
                al[1] = cvt2bf(e2 - bflo(ah[1]), e3 - bfhi(ah[1]));
                al[2] = cvt2bf(e4 - bflo(ah[2]), e5 - bfhi(ah[2]));
                al[3] = cvt2bf(e6 - bflo(ah[3]), e7 - bfhi(ah[3]));

                mma16(oc[mt], ah, vh0, vh1);
                mma16(oc[mt], al, vh0, vh1);
                mma16(oc[mt], ah, vl0, vl1);
            }
        }
    }

    // ---- reduce row sums across quads, normalize, write ----
#pragma unroll
    for (int mt = 0; mt < 2; mt++) {
        float l0 = ls[mt][0], l1 = ls[mt][1];
        l0 += __shfl_xor_sync(0xffffffffu, l0, 1);
        l0 += __shfl_xor_sync(0xffffffffu, l0, 2);
        l1 += __shfl_xor_sync(0xffffffffu, l1, 1);
        l1 += __shfl_xor_sync(0xffffffffu, l1, 2);
        float i0 = 1.f / l0, i1 = 1.f / l1;
        int rb = slab * 128 + w * 32 + mt * 16;
        float* d0 = g_att + ((size_t)(b * SS + rb + g)) * EE + h * DD + 2 * qc;
        float* d1 = g_att + ((size_t)(b * SS + rb + 8 + g)) * EE + h * DD + 2 * qc;
        *reinterpret_cast<float2*>(d0) = make_float2(oc[mt][0] * i0, oc[mt][1] * i0);
        *reinterpret_cast<float2*>(d1) = make_float2(oc[mt][2] * i1, oc[mt][3] * i1);
    }
}

// ---------------------------------------------------------------------------
// GEMM via mma.sync (bf16 hi/lo split): out = g_att @ W^T.
// M=4096, N=256, K=256. CTA = 64m x 64n, 4 warps (warp = m16), 16 k16 steps.
// W block staged in dynamic SMEM as bf16x2 k-pair words, pitch 132 words/row
// (132 mod 32 = 4 -> fragment banks 4g+qc all distinct, conflict-free).
// A fragments loaded from GMEM fp32 (L1-resident) + split inline; one A-frag
// feeds 8 n-tiles x 3 split mma16. 3-term: AhWh + AlWh + AhWl.
// ---------------------------------------------------------------------------
#define WPITCH 132
constexpr int GEMM_SMEM = 2 * 64 * WPITCH * 4;   // 67584 bytes

__global__ void __launch_bounds__(128) gemm_kernel(const float* __restrict__ W,
                                                   float* __restrict__ out) {
    extern __shared__ uint32_t sW[];
    uint32_t* sWh = sW;
    uint32_t* sWl = sW + 64 * WPITCH;

    int tid = threadIdx.x;
    int w   = tid >> 5;
    int ln  = tid & 31;
    int g   = ln >> 2;
    int qc  = ln & 3;
    int n0 = blockIdx.x * 64, m0 = blockIdx.y * 64;

    // ---- stage W block [64 n][128 kp] as split bf16x2 words ----
#pragma unroll
    for (int it = 0; it < 64; it++) {
        int idx = tid + it * 128;      // 8192 words
        int n  = idx >> 7;
        int kp = idx & 127;
        float2 v = *reinterpret_cast<const float2*>(&W[(size_t)(n0 + n) * EE + 2 * kp]);
        uint32_t hw = cvt2bf(v.x, v.y);
        uint32_t lw = cvt2bf(v.x - bflo(hw), v.y - bfhi(hw));
        sWh[n * WPITCH + kp] = hw;
        sWl[n * WPITCH + kp] = lw;
    }
    __syncthreads();

    float acc[8][4];
#pragma unroll
    for (int j = 0; j < 8; j++)
#pragma unroll
        for (int i = 0; i < 4; i++) acc[j][i] = 0.f;

    int row0 = m0 + w * 16 + g;
    const float* A0 = &g_att[(size_t)row0 * EE];
    const float* A1 = A0 + 8 * EE;

    for (int t = 0; t < 16; t++) {
        float2 f0 = *reinterpret_cast<const float2*>(&A0[t * 16 + 2 * qc]);
        float2 f1 = *reinterpret_cast<const float2*>(&A1[t * 16 + 2 * qc]);
        float2 f2 = *reinterpret_cast<const float2*>(&A0[t * 16 + 8 + 2 * qc]);
        float2 f3 = *reinterpret_cast<const float2*>(&A1[t * 16 + 8 + 2 * qc]);

        uint32_t ah[4], al[4];
        ah[0] = cvt2bf(f0.x, f0.y);
        ah[1] = cvt2bf(f1.x, f1.y);
        ah[2] = cvt2bf(f2.x, f2.y);
        ah[3] = cvt2bf(f3.x, f3.y);
        al[0] = cvt2bf(f0.x - bflo(ah[0]), f0.y - bfhi(ah[0]));
        al[1] = cvt2bf(f1.x - bflo(ah[1]), f1.y - bfhi(ah[1]));
        al[2] = cvt2bf(f2.x - bflo(ah[2]), f2.y - bfhi(ah[2]));
        al[3] = cvt2bf(f3.x - bflo(ah[3]), f3.y - bfhi(ah[3]));

#pragma unroll
        for (int j = 0; j < 8; j++) {
            int nrow = j * 8 + g;
            uint32_t bh0 = sWh[nrow * WPITCH + t * 8 + qc];
            uint32_t bh1 = sWh[nrow * WPITCH + t * 8 + 4 + qc];
            uint32_t bl0 = sWl[nrow * WPITCH + t * 8 + qc];
            uint32_t bl1 = sWl[nrow * WPITCH + t * 8 + 4 + qc];
            mma16(acc[j], ah, bh0, bh1);
            mma16(acc[j], al, bh0, bh1);
            mma16(acc[j], ah, bl0, bl1);
        }
    }

    // ---- write C fragments: c0,c1 = (row g, cols 2qc..2qc+1); c2,c3 = row g+8
#pragma unroll
    for (int j = 0; j < 8; j++) {
        float* r0 = &out[(size_t)row0 * EE + n0 + j * 8 + 2 * qc];
        float* r1 = &out[(size_t)(row0 + 8) * EE + n0 + j * 8 + 2 * qc];
        *reinterpret_cast<float2*>(r0) = make_float2(acc[j][0], acc[j][1]);
        *reinterpret_cast<float2*>(r1) = make_float2(acc[j][2], acc[j][3]);
    }
}

// ---------------------------------------------------------------------------
extern "C" void kernel_launch(void* const* d_in, const int* in_sizes, int n_in,
                              void* d_out, int out_size) {
    const float* x = nullptr;
    const float* theta = nullptr;
    const float* w = nullptr;
    for (int i = 0; i < n_in; i++) {
        if (in_sizes[i] == NROWS * DD)      x = (const float*)d_in[i];
        else if (in_sizes[i] == DD)         theta = (const float*)d_in[i];
        else if (in_sizes[i] == EE * EE)    w = (const float*)d_in[i];
    }

    // Host-side attribute set: graph-capture-safe, deterministic.
    cudaFuncSetAttribute(gemm_kernel,
                         cudaFuncAttributeMaxDynamicSharedMemorySize, GEMM_SMEM);

    attn_kernel<<<dim3(BB * HH, 8), 128>>>(x, theta);
    gemm_kernel<<<dim3(EE / 64, BB * SS / 64), 128, GEMM_SMEM>>>(w, (float*)d_out);
}